// round 8
// baseline (speedup 1.0000x reference)
#include <cuda_runtime.h>
#include <math.h>

// ---------------- problem constants ----------------
// B=4, C=3, H=W=768, P=128, S=64, K=31, n_h=n_w=11, N=121
#define TOTAL   7077888          // 4*3*768*768
#define IMGHW   589824           // 768*768
#define NPIX    961              // 31*31

typedef unsigned long long u64;

// ---------------- device scratch ----------------
__device__ float g_kern[363 * NPIX];      // flipped+normalized PSFs, [n*3+c][31*31]
__device__ float g_xlin[TOTAL];           // (relu(x)+eps)^gamma
__device__ float g_acc[4 * TOTAL];        // 4 parity planes (zero-init .bss; only valid entries written)

__device__ __forceinline__ float hannf(int r) {   // fast hann (conv/fin hot path)
    return 0.5f * (1.0f - __cosf((6.28318530717958647692f * (float)r) * 0.0078125f));
}

__device__ __forceinline__ double dpow_i(double x, int e) {
    double r = 1.0;
    for (int q = 0; q < e; q++) r *= x;
    return r;
}

// packed 2xfp32 FMA (sm_103a FFMA2)
__device__ __forceinline__ void ffma2(u64& acc, u64 k2, u64 w2) {
    asm("fma.rn.f32x2 %0, %1, %2, %0;" : "+l"(acc) : "l"(k2), "l"(w2));
}
__device__ __forceinline__ float u64lo(u64 v) { return __uint_as_float((unsigned)v); }
__device__ __forceinline__ float u64hi(u64 v) { return __uint_as_float((unsigned)(v >> 32)); }

// block-wide sum over 1024 threads (shfl + 33-float smem scratch)
__device__ __forceinline__ float blockReduce(float v, float* sm) {
    __syncthreads();
#pragma unroll
    for (int o = 16; o > 0; o >>= 1) v += __shfl_down_sync(0xffffffffu, v, o);
    int w = threadIdx.x >> 5;
    if ((threadIdx.x & 31) == 0) sm[w] = v;
    __syncthreads();
    if (threadIdx.x < 32) {
        float r = sm[threadIdx.x];
#pragma unroll
        for (int o = 16; o > 0; o >>= 1) r += __shfl_down_sync(0xffffffffu, r, o);
        if (threadIdx.x == 0) sm[32] = r;
    }
    __syncthreads();
    return sm[32];
}

// ---------------- stage 0: fused basis + MLP + PSF (one kernel, 363 blocks) ----------------
// CRITICAL numerics: linspace/r2 replicate numpy's exact IEEE sequence (no FMA contraction) —
// 16 pixels sit EXACTLY on r2==1 (9-12-15 triple); membership decided by last-ulp rounding.
__global__ void setup_kernel(const float* __restrict__ w1, const float* __restrict__ b1,
                             const float* __restrict__ w2, const float* __restrict__ b2,
                             const float* __restrict__ w3, const float* __restrict__ b3) {
    __shared__ float red[33];
    __shared__ float s1[64], s2[64], scoef[14];
    __shared__ float fre[NPIX], fim[NPIX], Gre[NPIX], Gim[NPIX];
    __shared__ float twr[31], twi[31];

    int t = threadIdx.x;
    bool act = (t < NPIX);
    int blk = blockIdx.x;            // n*3 + c
    int n = blk / 3, c = blk % 3;

    // ---- inline MLP for this block's grid position n ----
    {
        int iy = n / 11, jx = n % 11;
        float cy = (float)((((double)(iy * 64) + 64.0) / 768.0) * 2.0 - 1.0);
        float cx = (float)((((double)(jx * 64) + 64.0) / 768.0) * 2.0 - 1.0);
        if (t < 64) s1[t] = tanhf(cy * w1[t] + cx * w1[64 + t] + b1[t]);
        __syncthreads();
        if (t < 64) {
            float a = b2[t];
            for (int k = 0; k < 64; k++) a += s1[k] * w2[k * 64 + t];
            s2[t] = tanhf(a);
        }
        __syncthreads();
        if (t < 14) {
            float o = b3[t];
            for (int k = 0; k < 64; k++) o += s2[k] * w3[k * 14 + t];
            scoef[t] = o;
        }
        if (t < 31) {
            float ang = -6.28318530717958647692f * (float)t / 31.0f;
            twr[t] = cosf(ang);
            twi[t] = sinf(ang);
        }
        __syncthreads();
    }

    // ---- basis + phase (per-pixel, block reductions for rms) ----
    int i = t / 31, j = t % 31;
    double step = 2.0 / 30.0;
    double x = 0.0, y = 0.0;
    float m = 0.0f;
    if (act) {
        x = (j == 30) ? 1.0 : __dadd_rn(__dmul_rn((double)j, step), -1.0);
        y = (i == 30) ? 1.0 : __dadd_rn(__dmul_rn((double)i, step), -1.0);
        double r2 = __dadd_rn(__dmul_rn(x, x), __dmul_rn(y, y));
        m = (r2 <= 1.0) ? 1.0f : 0.0f;
    }
    float mc = blockReduce(act ? m : 0.0f, red);

    float wl = 0.53f / ((c == 0) ? 0.61f : ((c == 1) ? 0.53f : 0.47f));
    float ph = 0.0f;
    int z = 0;
    for (int deg = 1; deg <= 4; deg++) {
        for (int k = 0; k <= deg; k++) {
            float bb = 0.0f;
            if (act) bb = (float)(dpow_i(x, deg - k) * dpow_i(y, k)) * m;
            float ss = blockReduce(bb * bb, red);
            float rms = sqrtf(ss / mc) + 1e-8f;
            if (act) ph = fmaf(scoef[z], bb / rms, ph);
            z++;
        }
    }

    if (act) {
        float th = 6.28318530717958647692f * (wl * ph);
        float sn, cs;
        sincosf(th, &sn, &cs);
        fre[t] = m * cs;
        fim[t] = m * sn;
    }
    __syncthreads();

    // ---- 31x31 separable DFT, |.|^2, normalize, fftshift+flip store ----
    int u = t / 31, v = t % 31;
    if (act) {
        float gr = 0.0f, gi = 0.0f;
        int m2 = 0;
        for (int i2 = 0; i2 < 31; i2++) {
            float tr = twr[m2], ti = twi[m2];
            float ar = fre[i2 * 31 + v], ai = fim[i2 * 31 + v];
            gr = fmaf(ar, tr, gr); gr = fmaf(-ai, ti, gr);
            gi = fmaf(ar, ti, gi); gi = fmaf(ai, tr, gi);
            m2 += u; if (m2 >= 31) m2 -= 31;
        }
        Gre[t] = gr; Gim[t] = gi;
    }
    __syncthreads();

    float mag = 0.0f;
    if (act) {
        float fr = 0.0f, fi = 0.0f;
        int m2 = 0;
        for (int j2 = 0; j2 < 31; j2++) {
            float tr = twr[m2], ti = twi[m2];
            float gr = Gre[u * 31 + j2], gi = Gim[u * 31 + j2];
            fr = fmaf(gr, tr, fr); fr = fmaf(-gi, ti, fr);
            fi = fmaf(gr, ti, fi); fi = fmaf(gi, tr, fi);
            m2 += v; if (m2 >= 31) m2 -= 31;
        }
        mag = fr * fr + fi * fi;
    }
    float tot = blockReduce(act ? mag : 0.0f, red);
    float inv = 1.0f / (tot + 1e-6f);
    if (act) {
        int pu = u + 15; if (pu >= 31) pu -= 31;   // fftshift
        int pv = v + 15; if (pv >= 31) pv -= 31;
        g_kern[blk * NPIX + (30 - pu) * 31 + (30 - pv)] = mag * inv;  // flip
    }
}

// ---------------- stage 1: gamma-linearize (float4 + fast pow) ----------------
__global__ void prep_kernel(const float4* __restrict__ x, const float* __restrict__ gp) {
    int id = blockIdx.x * blockDim.x + threadIdx.x;      // < TOTAL/4
    float g = *gp;
    float4 v = x[id];
    float4 o;
    o.x = __expf(g * __logf(fmaxf(v.x, 0.0f) + 1e-6f));
    o.y = __expf(g * __logf(fmaxf(v.y, 0.0f) + 1e-6f));
    o.z = __expf(g * __logf(fmaxf(v.z, 0.0f) + 1e-6f));
    o.w = __expf(g * __logf(fmaxf(v.w, 0.0f) + 1e-6f));
    ((float4*)g_xlin)[id] = o;
}

// ---------------- stage 2: 31x31 depthwise conv, 16 rows/thread, FFMA2 ----------------
__global__ void __launch_bounds__(256) conv_kernel() {
    __shared__ __align__(16) float sInT[62 * 158];   // [col][row] transposed, 39.2 KB
    __shared__ __align__(16) float2 sKd[31 * 32];    // duplicated taps (k,k), [dc][dr], 7.9 KB

    int id = blockIdx.x;
    int tile = id & 3;
    int pcc = id >> 2;
    int c = pcc % 3;
    int t2 = pcc / 3;
    int n = t2 % 121;
    int b = t2 / 121;
    int ip = n / 11, jp = n % 11;
    int C0 = tile << 5;          // 0,32,64,96
    int tid = threadIdx.x;

    const float* gk = g_kern + (n * 3 + c) * NPIX;
    for (int q = tid; q < NPIX; q += 256) {
        int dr = q / 31, dc2 = q - dr * 31;
        float k = gk[q];
        sKd[dc2 * 32 + dr] = make_float2(k, k);
    }

    const float* gxp = g_xlin + (size_t)(b * 3 + c) * IMGHW;
    for (int q = tid; q < 158 * 62; q += 256) {
        int rr = q / 62;
        int cc = q - rr * 62;
        int sy = rr - 15;
        int sx = C0 + cc - 15;
        float v = 0.0f;
        if ((unsigned)sy < 128u && (unsigned)sx < 128u)
            v = gxp[(ip * 64 + sy) * 768 + (jp * 64 + sx)];
        sInT[cc * 158 + rr] = v;
    }
    __syncthreads();

    int tx = tid & 31, ty = tid >> 5;    // ty 0..7 owns rows 16ty..16ty+15
    u64 A[8], O[9];
#pragma unroll
    for (int q = 0; q < 8; q++) A[q] = 0;
#pragma unroll
    for (int q = 0; q < 9; q++) O[q] = 0;

#pragma unroll 1
    for (int dc = 0; dc < 31; ++dc) {
        const u64* colp = (const u64*)(sInT + (tx + dc) * 158) + ty * 8;
        const u64* kp = (const u64*)(sKd + dc * 32);
        u64 pe[16];
#pragma unroll
        for (int j = 0; j < 9; j++) pe[j] = colp[j];

#pragma unroll
        for (int d = 0; d < 15; d++) {
            u64 ke = kp[2 * d];
#pragma unroll
            for (int j = 0; j < 8; j++) ffma2(A[j], ke, pe[(d + j) & 15]);
            u64 ko = kp[2 * d + 1];
#pragma unroll
            for (int j = 0; j < 9; j++) ffma2(O[j], ko, pe[(d + j) & 15]);
            if (d < 14) pe[(d + 9) & 15] = colp[d + 9];
        }
        {
            u64 ke = kp[30];
#pragma unroll
            for (int j = 0; j < 8; j++) ffma2(A[j], ke, pe[(15 + j) & 15]);
        }
    }

    int plane = ((ip & 1) << 1) | (jp & 1);
    float hc = hannf(C0 + tx);
    int gx0 = jp * 64 + C0 + tx;
    float* outp = g_acc + (size_t)plane * TOTAL + (size_t)(b * 3 + c) * IMGHW;
#pragma unroll
    for (int j = 0; j < 8; j++) {
        int pr0 = ty * 16 + 2 * j;
        float o0 = u64lo(A[j]) + u64hi(O[j]);
        float o1 = u64hi(A[j]) + u64lo(O[j + 1]);
        outp[(ip * 64 + pr0) * 768 + gx0]     = o0 * (hannf(pr0) * hc);
        outp[(ip * 64 + pr0 + 1) * 768 + gx0] = o1 * (hannf(pr0 + 1) * hc);
    }
}

// ---------------- stage 3: gather planes, window-normalize, inverse gamma (float4) ----------------
__global__ void fin_kernel(float4* __restrict__ out, const float* __restrict__ gp) {
    int id = blockIdx.x * blockDim.x + threadIdx.x;      // < TOTAL/4
    float ig = 1.0f / (*gp);
    int e0 = id * 4;
    int xc0 = e0 % 768;
    int y = (e0 / 768) % 768;

    float ny = 0.0f;
    int i1 = y >> 6;
    if (i1 <= 10) ny += hannf(y - i1 * 64);
    if (i1 >= 1)  ny += hannf(y - (i1 - 1) * 64);

    const float4* a0 = (const float4*)g_acc;
    float4 p0 = a0[id];
    float4 p1 = a0[(TOTAL >> 2) + id];
    float4 p2 = a0[(TOTAL >> 1) + id];
    float4 p3 = a0[3 * (TOTAL >> 2) + id];

    float4 r;
    float* rr = &r.x;
    const float* q0 = &p0.x; const float* q1 = &p1.x;
    const float* q2 = &p2.x; const float* q3 = &p3.x;
#pragma unroll
    for (int k = 0; k < 4; k++) {
        int xcol = xc0 + k;
        float nx = 0.0f;
        int j1 = xcol >> 6;
        if (j1 <= 10) nx += hannf(xcol - j1 * 64);
        if (j1 >= 1)  nx += hannf(xcol - (j1 - 1) * 64);
        float s = q0[k] + q1[k] + q2[k] + q3[k];
        float v = s / (ny * nx + 1e-6f);
        rr[k] = __expf(ig * __logf(fmaxf(v, 0.0f) + 1e-6f));
    }
    out[id] = r;
}

// ---------------- launch ----------------
extern "C" void kernel_launch(void* const* d_in, const int* in_sizes, int n_in,
                              void* d_out, int out_size) {
    const float* x  = (const float*)d_in[0];
    const float* w1 = (const float*)d_in[1];
    const float* b1 = (const float*)d_in[2];
    const float* w2 = (const float*)d_in[3];
    const float* b2 = (const float*)d_in[4];
    const float* w3 = (const float*)d_in[5];
    const float* b3 = (const float*)d_in[6];
    const float* gp = (const float*)d_in[7];

    setup_kernel<<<363, 1024>>>(w1, b1, w2, b2, w3, b3);
    prep_kernel<<<(TOTAL / 4) / 256, 256>>>((const float4*)x, gp);
    conv_kernel<<<5808, 256>>>();
    fin_kernel<<<(TOTAL / 4) / 256, 256>>>((float4*)d_out, gp);
}

// round 9
// speedup vs baseline: 1.0243x; 1.0243x over previous
#include <cuda_runtime.h>
#include <math.h>

// ---------------- problem constants ----------------
// B=4, C=3, H=W=768, P=128, S=64, K=31, n_h=n_w=11, N=121
#define TOTAL   7077888          // 4*3*768*768
#define IMGHW   589824           // 768*768
#define NPIX    961              // 31*31

typedef unsigned long long u64;

// ---------------- device scratch ----------------
__device__ float g_kern[363 * NPIX];      // flipped+normalized PSFs, [n*3+c][31*31]
__device__ float g_xlin[TOTAL];           // (relu(x)+eps)^gamma
__device__ float g_acc[4 * TOTAL];        // 4 parity planes (zero-init .bss; only valid entries written)

__device__ __forceinline__ float hannf(int r) {
    return 0.5f * (1.0f - __cosf((6.28318530717958647692f * (float)r) * 0.0078125f));
}

__device__ __forceinline__ double dpow_i(double x, int e) {
    double r = 1.0;
    for (int q = 0; q < e; q++) r *= x;
    return r;
}

// packed 2xfp32 FMA (sm_103a FFMA2)
__device__ __forceinline__ void ffma2(u64& acc, u64 k2, u64 w2) {
    asm("fma.rn.f32x2 %0, %1, %2, %0;" : "+l"(acc) : "l"(k2), "l"(w2));
}
__device__ __forceinline__ float u64lo(u64 v) { return __uint_as_float((unsigned)v); }
__device__ __forceinline__ float u64hi(u64 v) { return __uint_as_float((unsigned)(v >> 32)); }

// block-wide sum over 1024 threads
__device__ __forceinline__ float blockReduce(float v, float* sm) {
    __syncthreads();
#pragma unroll
    for (int o = 16; o > 0; o >>= 1) v += __shfl_down_sync(0xffffffffu, v, o);
    int w = threadIdx.x >> 5;
    if ((threadIdx.x & 31) == 0) sm[w] = v;
    __syncthreads();
    if (threadIdx.x < 32) {
        float r = sm[threadIdx.x];
#pragma unroll
        for (int o = 16; o > 0; o >>= 1) r += __shfl_down_sync(0xffffffffu, r, o);
        if (threadIdx.x == 0) sm[32] = r;
    }
    __syncthreads();
    return sm[32];
}

// ---------------- stage 0: fused basis + MLP + PSF ----------------
// CRITICAL numerics: linspace/r2 replicate numpy's exact IEEE sequence (no FMA contraction) —
// 16 pixels sit EXACTLY on r2==1 (9-12-15 triple); membership decided by last-ulp rounding.
__global__ void setup_kernel(const float* __restrict__ w1, const float* __restrict__ b1,
                             const float* __restrict__ w2, const float* __restrict__ b2,
                             const float* __restrict__ w3, const float* __restrict__ b3) {
    __shared__ float red[33];
    __shared__ float s1[64], s2[64], scoef[14];
    __shared__ float fre[NPIX], fim[NPIX], Gre[NPIX], Gim[NPIX];
    __shared__ float twr[31], twi[31];

    int t = threadIdx.x;
    bool act = (t < NPIX);
    int blk = blockIdx.x;            // n*3 + c
    int n = blk / 3, c = blk % 3;

    {
        int iy = n / 11, jx = n % 11;
        float cy = (float)((((double)(iy * 64) + 64.0) / 768.0) * 2.0 - 1.0);
        float cx = (float)((((double)(jx * 64) + 64.0) / 768.0) * 2.0 - 1.0);
        if (t < 64) s1[t] = tanhf(cy * w1[t] + cx * w1[64 + t] + b1[t]);
        __syncthreads();
        if (t < 64) {
            float a = b2[t];
            for (int k = 0; k < 64; k++) a += s1[k] * w2[k * 64 + t];
            s2[t] = tanhf(a);
        }
        __syncthreads();
        if (t < 14) {
            float o = b3[t];
            for (int k = 0; k < 64; k++) o += s2[k] * w3[k * 14 + t];
            scoef[t] = o;
        }
        if (t < 31) {
            float ang = -6.28318530717958647692f * (float)t / 31.0f;
            twr[t] = cosf(ang);
            twi[t] = sinf(ang);
        }
        __syncthreads();
    }

    int i = t / 31, j = t % 31;
    double step = 2.0 / 30.0;
    double x = 0.0, y = 0.0;
    float m = 0.0f;
    if (act) {
        x = (j == 30) ? 1.0 : __dadd_rn(__dmul_rn((double)j, step), -1.0);
        y = (i == 30) ? 1.0 : __dadd_rn(__dmul_rn((double)i, step), -1.0);
        double r2 = __dadd_rn(__dmul_rn(x, x), __dmul_rn(y, y));
        m = (r2 <= 1.0) ? 1.0f : 0.0f;
    }
    float mc = blockReduce(act ? m : 0.0f, red);

    float wl = 0.53f / ((c == 0) ? 0.61f : ((c == 1) ? 0.53f : 0.47f));
    float ph = 0.0f;
    int z = 0;
    for (int deg = 1; deg <= 4; deg++) {
        for (int k = 0; k <= deg; k++) {
            float bb = 0.0f;
            if (act) bb = (float)(dpow_i(x, deg - k) * dpow_i(y, k)) * m;
            float ss = blockReduce(bb * bb, red);
            float rms = sqrtf(ss / mc) + 1e-8f;
            if (act) ph = fmaf(scoef[z], bb / rms, ph);
            z++;
        }
    }

    if (act) {
        float th = 6.28318530717958647692f * (wl * ph);
        float sn, cs;
        sincosf(th, &sn, &cs);
        fre[t] = m * cs;
        fim[t] = m * sn;
    }
    __syncthreads();

    int u = t / 31, v = t % 31;
    if (act) {
        float gr = 0.0f, gi = 0.0f;
        int m2 = 0;
        for (int i2 = 0; i2 < 31; i2++) {
            float tr = twr[m2], ti = twi[m2];
            float ar = fre[i2 * 31 + v], ai = fim[i2 * 31 + v];
            gr = fmaf(ar, tr, gr); gr = fmaf(-ai, ti, gr);
            gi = fmaf(ar, ti, gi); gi = fmaf(ai, tr, gi);
            m2 += u; if (m2 >= 31) m2 -= 31;
        }
        Gre[t] = gr; Gim[t] = gi;
    }
    __syncthreads();

    float mag = 0.0f;
    if (act) {
        float fr = 0.0f, fi = 0.0f;
        int m2 = 0;
        for (int j2 = 0; j2 < 31; j2++) {
            float tr = twr[m2], ti = twi[m2];
            float gr = Gre[u * 31 + j2], gi = Gim[u * 31 + j2];
            fr = fmaf(gr, tr, fr); fr = fmaf(-gi, ti, fr);
            fi = fmaf(gr, ti, fi); fi = fmaf(gi, tr, fi);
            m2 += v; if (m2 >= 31) m2 -= 31;
        }
        mag = fr * fr + fi * fi;
    }
    float tot = blockReduce(act ? mag : 0.0f, red);
    float inv = 1.0f / (tot + 1e-6f);
    if (act) {
        int pu = u + 15; if (pu >= 31) pu -= 31;
        int pv = v + 15; if (pv >= 31) pv -= 31;
        g_kern[blk * NPIX + (30 - pu) * 31 + (30 - pv)] = mag * inv;
    }
}

// ---------------- stage 1: gamma-linearize (float4 + fast pow) ----------------
__global__ void prep_kernel(const float4* __restrict__ x, const float* __restrict__ gp) {
    int id = blockIdx.x * blockDim.x + threadIdx.x;
    float g = *gp;
    float4 v = x[id];
    float4 o;
    o.x = __expf(g * __logf(fmaxf(v.x, 0.0f) + 1e-6f));
    o.y = __expf(g * __logf(fmaxf(v.y, 0.0f) + 1e-6f));
    o.z = __expf(g * __logf(fmaxf(v.z, 0.0f) + 1e-6f));
    o.w = __expf(g * __logf(fmaxf(v.w, 0.0f) + 1e-6f));
    ((float4*)g_xlin)[id] = o;
}

// ---------------- stage 2: 31x31 depthwise conv, 16 rows/thread, FFMA2 + LDS.128 ----------------
// Transposed column stride = 164 floats (656B = 41 x 16B: 16B-aligned AND odd 16B count
// => LDS.128 across the warp hits all 32 banks conflict-free). Taps staged as duplicated
// (k,k) pairs so one LDS.128 fetches the (even,odd) tap pair for a d-step.
#define CSTR 164
__global__ void __launch_bounds__(256) conv_kernel() {
    __shared__ __align__(16) float sInT[62 * CSTR];  // [col][row] transposed, 40.7 KB
    __shared__ __align__(16) float2 sKd[31 * 32];    // duplicated taps (k,k), [dc][dr], 7.9 KB

    int id = blockIdx.x;
    int tile = id & 3;
    int pcc = id >> 2;
    int c = pcc % 3;
    int t2 = pcc / 3;
    int n = t2 % 121;
    int b = t2 / 121;
    int ip = n / 11, jp = n % 11;
    int C0 = tile << 5;          // 0,32,64,96
    int tid = threadIdx.x;

    const float* gk = g_kern + (n * 3 + c) * NPIX;
    for (int q = tid; q < NPIX; q += 256) {
        int dr = q / 31, dc2 = q - dr * 31;
        float k = gk[q];
        sKd[dc2 * 32 + dr] = make_float2(k, k);
    }

    const float* gxp = g_xlin + (size_t)(b * 3 + c) * IMGHW;
    for (int q = tid; q < 158 * 62; q += 256) {
        int rr = q / 62;
        int cc = q - rr * 62;
        int sy = rr - 15;
        int sx = C0 + cc - 15;
        float v = 0.0f;
        if ((unsigned)sy < 128u && (unsigned)sx < 128u)
            v = gxp[(ip * 64 + sy) * 768 + (jp * 64 + sx)];
        sInT[cc * CSTR + rr] = v;
    }
    __syncthreads();

    int tx = tid & 31, ty = tid >> 5;    // ty 0..7 owns rows 16ty..16ty+15
    u64 A[8], O[9];
#pragma unroll
    for (int q = 0; q < 8; q++) A[q] = 0;
#pragma unroll
    for (int q = 0; q < 9; q++) O[q] = 0;

#pragma unroll 1
    for (int dc = 0; dc < 31; ++dc) {
        const u64* colp = (const u64*)(sInT + (tx + dc) * CSTR) + ty * 8;
        const ulonglong2* kp2 = (const ulonglong2*)(sKd + dc * 32);
        u64 pe[16];
        // preload elements 0..9 (5x LDS.128)
#pragma unroll
        for (int m2 = 0; m2 < 5; m2++) {
            ulonglong2 w = ((const ulonglong2*)colp)[m2];
            pe[2 * m2] = w.x;
            pe[2 * m2 + 1] = w.y;
        }

#pragma unroll
        for (int d = 0; d < 15; d++) {
            ulonglong2 kk = kp2[d];          // (k_even[d], k_odd[d]) duplicated pairs
#pragma unroll
            for (int j = 0; j < 8; j++) ffma2(A[j], kk.x, pe[(d + j) & 15]);
#pragma unroll
            for (int j = 0; j < 9; j++) ffma2(O[j], kk.y, pe[(d + j) & 15]);
            if ((d & 1) == 0 && d <= 12) {   // refill elements d+10, d+11
                ulonglong2 w = ((const ulonglong2*)colp)[(d + 10) >> 1];
                pe[(d + 10) & 15] = w.x;
                pe[(d + 11) & 15] = w.y;
            }
        }
        {
            u64 ke = ((const u64*)kp2)[30];  // final even tap dr=30
#pragma unroll
            for (int j = 0; j < 8; j++) ffma2(A[j], ke, pe[(15 + j) & 15]);
        }
    }

    int plane = ((ip & 1) << 1) | (jp & 1);
    float hc = hannf(C0 + tx);
    int gx0 = jp * 64 + C0 + tx;
    float* outp = g_acc + (size_t)plane * TOTAL + (size_t)(b * 3 + c) * IMGHW;
#pragma unroll
    for (int j = 0; j < 8; j++) {
        int pr0 = ty * 16 + 2 * j;
        float o0 = u64lo(A[j]) + u64hi(O[j]);
        float o1 = u64hi(A[j]) + u64lo(O[j + 1]);
        outp[(ip * 64 + pr0) * 768 + gx0]     = o0 * (hannf(pr0) * hc);
        outp[(ip * 64 + pr0 + 1) * 768 + gx0] = o1 * (hannf(pr0 + 1) * hc);
    }
}

// ---------------- stage 3: gather planes, window-normalize, inverse gamma (float4) ----------------
__global__ void fin_kernel(float4* __restrict__ out, const float* __restrict__ gp) {
    int id = blockIdx.x * blockDim.x + threadIdx.x;
    float ig = 1.0f / (*gp);
    int e0 = id * 4;
    int xc0 = e0 % 768;
    int y = (e0 / 768) % 768;

    float ny = 0.0f;
    int i1 = y >> 6;
    if (i1 <= 10) ny += hannf(y - i1 * 64);
    if (i1 >= 1)  ny += hannf(y - (i1 - 1) * 64);

    const float4* a0 = (const float4*)g_acc;
    float4 p0 = a0[id];
    float4 p1 = a0[(TOTAL >> 2) + id];
    float4 p2 = a0[(TOTAL >> 1) + id];
    float4 p3 = a0[3 * (TOTAL >> 2) + id];

    float4 r;
    float* rr = &r.x;
    const float* q0 = &p0.x; const float* q1 = &p1.x;
    const float* q2 = &p2.x; const float* q3 = &p3.x;
#pragma unroll
    for (int k = 0; k < 4; k++) {
        int xcol = xc0 + k;
        float nx = 0.0f;
        int j1 = xcol >> 6;
        if (j1 <= 10) nx += hannf(xcol - j1 * 64);
        if (j1 >= 1)  nx += hannf(xcol - (j1 - 1) * 64);
        float s = q0[k] + q1[k] + q2[k] + q3[k];
        float v = s / (ny * nx + 1e-6f);
        rr[k] = __expf(ig * __logf(fmaxf(v, 0.0f) + 1e-6f));
    }
    out[id] = r;
}

// ---------------- launch ----------------
extern "C" void kernel_launch(void* const* d_in, const int* in_sizes, int n_in,
                              void* d_out, int out_size) {
    const float* x  = (const float*)d_in[0];
    const float* w1 = (const float*)d_in[1];
    const float* b1 = (const float*)d_in[2];
    const float* w2 = (const float*)d_in[3];
    const float* b2 = (const float*)d_in[4];
    const float* w3 = (const float*)d_in[5];
    const float* b3 = (const float*)d_in[6];
    const float* gp = (const float*)d_in[7];

    setup_kernel<<<363, 1024>>>(w1, b1, w2, b2, w3, b3);
    prep_kernel<<<(TOTAL / 4) / 256, 256>>>((const float4*)x, gp);
    conv_kernel<<<5808, 256>>>();
    fin_kernel<<<(TOTAL / 4) / 256, 256>>>((float4*)d_out, gp);
}